// round 4
// baseline (speedup 1.0000x reference)
#include <cuda_runtime.h>

// DynamicHead: per-sample grouped 1x1 conv (KERNEL_SIZE=1, PAD=0).
// f:      [B=8, C=400, H=128, W=128] fp32   (read exactly once, 210 MB)
// kernel: [B=8, N=50, CPG=8, 1, 1]   fp32   (12.8 KB, L1-resident)
// out:    [B=8, N=50, H=128, W=128]  fp32   (written once, 26 MB)
//
// HBM-bound at the L2<->DRAM path (R3 finding: 6.18 TB/s ceiling independent
// of occupancy/waves). This round: streaming cache policy — __ldcs for the
// use-once read stream, __stcs for the output — to cut L2 thrash between the
// read stream and dirty output writebacks.

#define N_      50
#define HW4_    4096                      // 128*128/4 float4 per plane
#define TOTAL4  (8 * 50 * HW4_)           // 1,638,400 output float4
#define TPB_    256

__global__ __launch_bounds__(TPB_)
void dynhead_1x1_cs(const float4* __restrict__ f4,
                    const float* __restrict__ kern,
                    float4* __restrict__ o4) {
    const int stride = gridDim.x * TPB_;
    for (int idx = blockIdx.x * TPB_ + threadIdx.x; idx < TOTAL4; idx += stride) {
        const int bn  = idx >> 12;            // idx / 4096  (0..399)
        const int pos = idx & (HW4_ - 1);
        const int b = bn / N_;                // magic-mul division
        const int n = bn - b * N_;

        // 8 group weights: warp-uniform, tiny, keep cached (L1 broadcast).
        const float* kp = kern + bn * 8;
        float w0 = __ldg(kp + 0), w1 = __ldg(kp + 1);
        float w2 = __ldg(kp + 2), w3 = __ldg(kp + 3);
        float w4 = __ldg(kp + 4), w5 = __ldg(kp + 5);
        float w6 = __ldg(kp + 6), w7 = __ldg(kp + 7);

        // 8 input planes, streaming (evict-first) loads: 8 independent LDG.128.
        const float4* fp = f4 + (((b * 400 + n * 8) << 12) + pos);
        const float4 v0 = __ldcs(fp + 0 * HW4_);
        const float4 v1 = __ldcs(fp + 1 * HW4_);
        const float4 v2 = __ldcs(fp + 2 * HW4_);
        const float4 v3 = __ldcs(fp + 3 * HW4_);
        const float4 v4 = __ldcs(fp + 4 * HW4_);
        const float4 v5 = __ldcs(fp + 5 * HW4_);
        const float4 v6 = __ldcs(fp + 6 * HW4_);
        const float4 v7 = __ldcs(fp + 7 * HW4_);

        float4 acc;
        acc.x = v0.x * w0; acc.y = v0.y * w0; acc.z = v0.z * w0; acc.w = v0.w * w0;
        acc.x = fmaf(w1, v1.x, acc.x); acc.y = fmaf(w1, v1.y, acc.y);
        acc.z = fmaf(w1, v1.z, acc.z); acc.w = fmaf(w1, v1.w, acc.w);
        acc.x = fmaf(w2, v2.x, acc.x); acc.y = fmaf(w2, v2.y, acc.y);
        acc.z = fmaf(w2, v2.z, acc.z); acc.w = fmaf(w2, v2.w, acc.w);
        acc.x = fmaf(w3, v3.x, acc.x); acc.y = fmaf(w3, v3.y, acc.y);
        acc.z = fmaf(w3, v3.z, acc.z); acc.w = fmaf(w3, v3.w, acc.w);
        acc.x = fmaf(w4, v4.x, acc.x); acc.y = fmaf(w4, v4.y, acc.y);
        acc.z = fmaf(w4, v4.z, acc.z); acc.w = fmaf(w4, v4.w, acc.w);
        acc.x = fmaf(w5, v5.x, acc.x); acc.y = fmaf(w5, v5.y, acc.y);
        acc.z = fmaf(w5, v5.z, acc.z); acc.w = fmaf(w5, v5.w, acc.w);
        acc.x = fmaf(w6, v6.x, acc.x); acc.y = fmaf(w6, v6.y, acc.y);
        acc.z = fmaf(w6, v6.z, acc.z); acc.w = fmaf(w6, v6.w, acc.w);
        acc.x = fmaf(w7, v7.x, acc.x); acc.y = fmaf(w7, v7.y, acc.y);
        acc.z = fmaf(w7, v7.z, acc.z); acc.w = fmaf(w7, v7.w, acc.w);

        // Streaming store: output is use-once from the kernel's perspective.
        __stcs(o4 + idx, acc);
    }
}

extern "C" void kernel_launch(void* const* d_in, const int* in_sizes, int n_in,
                              void* d_out, int out_size) {
    const float4* f4  = (const float4*)d_in[0];
    const float* kern = (const float*)d_in[1];
    float4* o4        = (float4*)d_out;

    // One resident wave: 8 CTAs/SM (256 thr -> 2048/SM cap). Host-side
    // attribute query happens at capture time only.
    int sm = 148;
    cudaDeviceGetAttribute(&sm, cudaDevAttrMultiProcessorCount, 0);
    dim3 grid(sm * 8);
    dynhead_1x1_cs<<<grid, TPB_>>>(f4, kern, o4);
}